// round 1
// baseline (speedup 1.0000x reference)
#include <cuda_runtime.h>
#include <math.h>

// Problem constants (fixed by the reference setup)
#define N_USER 60000
#define N_ITEM 40000
#define NN     (N_USER + N_ITEM)   // 100000 nodes
#define D      64
#define EMAX   800000
#define NB_SCAN ((NN + 1023) / 1024)   // 98 blocks

// ---- static device scratch (no allocations allowed) ----
__device__ float g_embA[NN * D];
__device__ float g_embB[NN * D];
__device__ float g_light[NN * D];
__device__ float g_norm[NN];
__device__ float g_rowsum[NN];
__device__ float g_cos[EMAX];
__device__ float g_mem[EMAX];
__device__ float g_aval[EMAX];
__device__ int   g_col[EMAX];
__device__ int   g_rowptr[NN + 1];
__device__ int   g_deg[NN];
__device__ int   g_bsum[128];
__device__ float g_U[2048 * D];
__device__ float g_I[2048 * D];

// ---------------- CSR build ----------------

__global__ void k_zero_deg() {
    int i = blockIdx.x * blockDim.x + threadIdx.x;
    if (i < NN) g_deg[i] = 0;
}

__global__ void k_hist(const int* __restrict__ src, int E) {
    for (int e = blockIdx.x * blockDim.x + threadIdx.x; e < E;
         e += gridDim.x * blockDim.x)
        atomicAdd(&g_deg[src[e]], 1);
}

// block-level exclusive scan of g_deg -> g_rowptr (local), block totals -> g_bsum
__global__ void k_scanA() {
    __shared__ int wsum[32];
    int i = blockIdx.x * 1024 + threadIdx.x;
    int lane = threadIdx.x & 31, wid = threadIdx.x >> 5;
    int v = (i < NN) ? g_deg[i] : 0;
    int x = v;
    #pragma unroll
    for (int o = 1; o < 32; o <<= 1) {
        int y = __shfl_up_sync(0xffffffffu, x, o);
        if (lane >= o) x += y;
    }
    if (lane == 31) wsum[wid] = x;
    __syncthreads();
    if (wid == 0) {
        int s = wsum[lane];
        #pragma unroll
        for (int o = 1; o < 32; o <<= 1) {
            int y = __shfl_up_sync(0xffffffffu, s, o);
            if (lane >= o) s += y;
        }
        wsum[lane] = s;
    }
    __syncthreads();
    int woff = (wid > 0) ? wsum[wid - 1] : 0;
    int incl = x + woff;
    if (i < NN) g_rowptr[i] = incl - v;  // exclusive, local to block
    if (threadIdx.x == 1023) g_bsum[blockIdx.x] = incl;
}

// exclusive scan of the (<=128) block sums, single block of 128 threads
__global__ void k_scanB(int nb) {
    int i = threadIdx.x;
    int v = (i < nb) ? g_bsum[i] : 0;
    int x = v;
    #pragma unroll
    for (int o = 1; o < 32; o <<= 1) {
        int y = __shfl_up_sync(0xffffffffu, x, o);
        if ((i & 31) >= o) x += y;
    }
    __shared__ int ws[4];
    if ((i & 31) == 31) ws[i >> 5] = x;
    __syncthreads();
    int off = 0;
    for (int w = 0; w < (i >> 5); w++) off += ws[w];
    if (i < nb) g_bsum[i] = x - v + off;  // exclusive
}

__global__ void k_scanC(int E) {
    int i = blockIdx.x * 1024 + threadIdx.x;
    if (i < NN) {
        g_rowptr[i] += g_bsum[blockIdx.x];
        g_deg[i] = 0;  // reset as scatter cursor
    }
    if (i == 0) g_rowptr[NN] = E;
}

__global__ void k_scatter(const int* __restrict__ src, const int* __restrict__ dst,
                          const float* __restrict__ adj, int E) {
    for (int e = blockIdx.x * blockDim.x + threadIdx.x; e < E;
         e += gridDim.x * blockDim.x) {
        int r = src[e];
        int pos = g_rowptr[r] + atomicAdd(&g_deg[r], 1);
        g_col[pos]  = dst[e];
        float a = adj[e];
        g_aval[pos] = a;
        g_mem[pos]  = a;   // memory starts as adjacency values
    }
}

// ---------------- init embeddings ----------------

__global__ void k_init_emb(const float* __restrict__ ue, const float* __restrict__ ie) {
    for (int i = blockIdx.x * blockDim.x + threadIdx.x; i < NN * D;
         i += gridDim.x * blockDim.x) {
        float v = (i < N_USER * D) ? ue[i] : ie[i - N_USER * D];
        g_embA[i]  = v;
        g_light[i] = v;   // embs[0] contribution to the mean-sum
    }
}

// ---------------- per-layer kernels (warp per node/row) ----------------

__global__ void k_norm(int cur) {
    const float* emb = cur ? g_embB : g_embA;
    int row = blockIdx.x * (blockDim.x >> 5) + (threadIdx.x >> 5);
    if (row >= NN) return;
    int lane = threadIdx.x & 31;
    float2 v = *(const float2*)(emb + row * D + lane * 2);
    float s = v.x * v.x + v.y * v.y;
    #pragma unroll
    for (int o = 16; o; o >>= 1) s += __shfl_xor_sync(0xffffffffu, s, o);
    if (lane == 0) g_norm[row] = sqrtf(s);
}

// pass 1: per-edge cosine + row L1 sums
__global__ void k_cos(int cur) {
    const float* emb = cur ? g_embB : g_embA;
    int row = blockIdx.x * (blockDim.x >> 5) + (threadIdx.x >> 5);
    if (row >= NN) return;
    int lane = threadIdx.x & 31;
    float2 es = *(const float2*)(emb + row * D + lane * 2);
    float nr = g_norm[row];
    int beg = g_rowptr[row], end = g_rowptr[row + 1];
    float rs = 0.f;
    for (int pos = beg; pos < end; pos++) {
        int c = g_col[pos];
        float2 ed = *(const float2*)(emb + c * D + lane * 2);
        float p = es.x * ed.x + es.y * ed.y;
        #pragma unroll
        for (int o = 16; o; o >>= 1) p += __shfl_xor_sync(0xffffffffu, p, o);
        float den = fmaxf(nr * g_norm[c], 1e-8f);
        float cs = p / den;
        if (lane == 0) g_cos[pos] = cs;
        rs += fabsf(cs);
    }
    if (lane == 0) g_rowsum[row] = rs;
}

// pass 2: coef -> prune -> mem EMA -> SpMM row accumulate (+ light sum)
__global__ void k_spmm(int cur, const float* __restrict__ W, const float* __restrict__ B) {
    const float* embin = cur ? g_embB : g_embA;
    float* embout      = cur ? g_embA : g_embB;
    int row = blockIdx.x * (blockDim.x >> 5) + (threadIdx.x >> 5);
    if (row >= NN) return;
    int lane = threadIdx.x & 31;
    float w0 = W[0], w1 = W[1], bb = B[0];
    float rsr = g_rowsum[row];
    float invr = 1.f / (rsr > 0.f ? rsr : 1.f);
    int beg = g_rowptr[row], end = g_rowptr[row + 1];
    float2 acc = make_float2(0.f, 0.f);
    for (int pos = beg; pos < end; pos++) {
        int c = g_col[pos];
        float cs = g_cos[pos];
        float rsd = g_rowsum[c];
        float c1 = cs * invr;                       // coef[e]
        float c2 = cs / (rsd > 0.f ? rsd : 1.f);    // coef[rev_perm[e]] (cos symmetric)
        float z = w0 * c1 + w1 * c2 + bb;           // sigmoid(z)>0.5 <=> z>0
        float coef = (z > 0.f) ? c1 : 0.f;
        float mold = g_mem[pos];
        float m = 0.5f * mold + 0.5f * coef;
        if (lane == 0) g_mem[pos] = m;
        float g = m * g_aval[pos];
        float2 ed = *(const float2*)(embin + c * D + lane * 2);
        acc.x += g * ed.x;
        acc.y += g * ed.y;
    }
    *(float2*)(embout + row * D + lane * 2) = acc;
    float2* lp = (float2*)(g_light + row * D + lane * 2);
    float2 lv = *lp;
    lv.x += acc.x; lv.y += acc.y;
    *lp = lv;
}

// ---------------- final: gather + sigmoid GEMM ----------------

__global__ void k_gather(const int* __restrict__ users, const int* __restrict__ items,
                         int Bu, int Bi) {
    int i = blockIdx.x * blockDim.x + threadIdx.x;
    int totU = Bu * D;
    if (i < totU) {
        int u = users[i >> 6];
        g_U[i] = 0.25f * g_light[u * D + (i & 63)];
    } else {
        int j = i - totU;
        if (j < Bi * D) {
            int it = items[j >> 6];
            g_I[j] = 0.25f * g_light[(N_USER + it) * D + (j & 63)];
        }
    }
}

__global__ void k_gemm(float* __restrict__ out, int Bu, int Bi) {
    __shared__ float As[64][65];
    __shared__ float Bs[64][65];
    int tx = threadIdx.x, ty = threadIdx.y;       // 16x16
    int t = ty * 16 + tx;
    int rowBase = blockIdx.y * 64, colBase = blockIdx.x * 64;
    #pragma unroll
    for (int i = 0; i < 4; i++) {
        int j = t + i * 256;       // float4 slot 0..1023
        int r = j >> 4;
        int kq = (j & 15) * 4;
        float4 a = (rowBase + r < Bu) ? *(const float4*)(g_U + (rowBase + r) * 64 + kq)
                                      : make_float4(0, 0, 0, 0);
        As[r][kq] = a.x; As[r][kq + 1] = a.y; As[r][kq + 2] = a.z; As[r][kq + 3] = a.w;
        float4 b = (colBase + r < Bi) ? *(const float4*)(g_I + (colBase + r) * 64 + kq)
                                      : make_float4(0, 0, 0, 0);
        Bs[r][kq] = b.x; Bs[r][kq + 1] = b.y; Bs[r][kq + 2] = b.z; Bs[r][kq + 3] = b.w;
    }
    __syncthreads();
    float acc[4][4] = {};
    #pragma unroll
    for (int k = 0; k < 64; k++) {
        float a0 = As[ty * 4 + 0][k], a1 = As[ty * 4 + 1][k];
        float a2 = As[ty * 4 + 2][k], a3 = As[ty * 4 + 3][k];
        float b0 = Bs[tx * 4 + 0][k], b1 = Bs[tx * 4 + 1][k];
        float b2 = Bs[tx * 4 + 2][k], b3 = Bs[tx * 4 + 3][k];
        acc[0][0] += a0 * b0; acc[0][1] += a0 * b1; acc[0][2] += a0 * b2; acc[0][3] += a0 * b3;
        acc[1][0] += a1 * b0; acc[1][1] += a1 * b1; acc[1][2] += a1 * b2; acc[1][3] += a1 * b3;
        acc[2][0] += a2 * b0; acc[2][1] += a2 * b1; acc[2][2] += a2 * b2; acc[2][3] += a2 * b3;
        acc[3][0] += a3 * b0; acc[3][1] += a3 * b1; acc[3][2] += a3 * b2; acc[3][3] += a3 * b3;
    }
    #pragma unroll
    for (int i = 0; i < 4; i++)
        #pragma unroll
        for (int j = 0; j < 4; j++) {
            int r = rowBase + ty * 4 + i;
            int c = colBase + tx * 4 + j;
            if (r < Bu && c < Bi)
                out[r * Bi + c] = 1.f / (1.f + expf(-acc[i][j]));
        }
}

// ---------------- launch ----------------

extern "C" void kernel_launch(void* const* d_in, const int* in_sizes, int n_in,
                              void* d_out, int out_size) {
    const int*   users    = (const int*)d_in[0];
    const int*   items    = (const int*)d_in[1];
    const float* user_emb = (const float*)d_in[2];
    const float* item_emb = (const float*)d_in[3];
    const float* W_prune  = (const float*)d_in[4];
    const float* b_prune  = (const float*)d_in[5];
    const int*   src      = (const int*)d_in[6];
    const int*   dst      = (const int*)d_in[7];
    // d_in[8] = rev_perm (unused: cosine is symmetric, so coef[rev] derives from rowsum[dst])
    const float* adj_vals = (const float*)d_in[9];

    int Bu = in_sizes[0];
    int Bi = in_sizes[1];
    int E  = in_sizes[6];

    float* out = (float*)d_out;

    int ebl = (E + 1023) / 1024;

    // CSR build
    k_zero_deg<<<NB_SCAN, 1024>>>();
    k_hist<<<ebl, 1024>>>(src, E);
    k_scanA<<<NB_SCAN, 1024>>>();
    k_scanB<<<1, 128>>>(NB_SCAN);
    k_scanC<<<NB_SCAN, 1024>>>(E);
    k_scatter<<<ebl, 1024>>>(src, dst, adj_vals, E);

    // init embeddings + light accumulator
    k_init_emb<<<(NN * D + 1023) / 1024, 1024>>>(user_emb, item_emb);

    // 3 propagation layers (warp per node row)
    int rowsblocks = (NN + 7) / 8;   // 8 warps per 256-thread block
    for (int l = 0; l < 3; l++) {
        int cur = l & 1;
        k_norm<<<rowsblocks, 256>>>(cur);
        k_cos<<<rowsblocks, 256>>>(cur);
        k_spmm<<<rowsblocks, 256>>>(cur, W_prune, b_prune);
    }

    // gather query embeddings (with /4 mean fold), then sigmoid GEMM
    int tot = (Bu + Bi) * D;
    k_gather<<<(tot + 255) / 256, 256>>>(users, items, Bu, Bi);
    dim3 gblk(16, 16);
    dim3 ggrd((Bi + 63) / 64, (Bu + 63) / 64);
    k_gemm<<<ggrd, gblk>>>(out, Bu, Bi);
}

// round 2
// speedup vs baseline: 1.5056x; 1.5056x over previous
#include <cuda_runtime.h>
#include <math.h>

// Problem constants (fixed by the reference setup)
#define N_USER 60000
#define N_ITEM 40000
#define NN     (N_USER + N_ITEM)   // 100000 nodes
#define D      64
#define EMAX   800000
#define NB_SCAN ((NN + 1023) / 1024)   // 98 blocks

// ---- static device scratch (no allocations allowed) ----
__device__ float g_embA[NN * D];
__device__ float g_embB[NN * D];
__device__ float g_light[NN * D];
__device__ float g_rnorm[NN];    // reciprocal norms
__device__ float g_rowsum[NN];   // L1 rowsum, then overwritten in-place with reciprocal
__device__ float g_cos[EMAX];
__device__ float g_mem[EMAX];
__device__ float g_aval[EMAX];
__device__ int   g_col[EMAX];
__device__ int   g_rowptr[NN + 1];
__device__ int   g_deg[NN];
__device__ int   g_bsum[128];
__device__ float g_U[2048 * D];
__device__ float g_I[2048 * D];

// ---------------- CSR build ----------------

__global__ void k_zero_deg() {
    int i = blockIdx.x * blockDim.x + threadIdx.x;
    if (i < NN) g_deg[i] = 0;
}

__global__ void k_hist(const int* __restrict__ src, int E) {
    for (int e = blockIdx.x * blockDim.x + threadIdx.x; e < E;
         e += gridDim.x * blockDim.x)
        atomicAdd(&g_deg[src[e]], 1);
}

__global__ void k_scanA() {
    __shared__ int wsum[32];
    int i = blockIdx.x * 1024 + threadIdx.x;
    int lane = threadIdx.x & 31, wid = threadIdx.x >> 5;
    int v = (i < NN) ? g_deg[i] : 0;
    int x = v;
    #pragma unroll
    for (int o = 1; o < 32; o <<= 1) {
        int y = __shfl_up_sync(0xffffffffu, x, o);
        if (lane >= o) x += y;
    }
    if (lane == 31) wsum[wid] = x;
    __syncthreads();
    if (wid == 0) {
        int s = wsum[lane];
        #pragma unroll
        for (int o = 1; o < 32; o <<= 1) {
            int y = __shfl_up_sync(0xffffffffu, s, o);
            if (lane >= o) s += y;
        }
        wsum[lane] = s;
    }
    __syncthreads();
    int woff = (wid > 0) ? wsum[wid - 1] : 0;
    int incl = x + woff;
    if (i < NN) g_rowptr[i] = incl - v;  // exclusive, local to block
    if (threadIdx.x == 1023) g_bsum[blockIdx.x] = incl;
}

__global__ void k_scanB(int nb) {
    int i = threadIdx.x;
    int v = (i < nb) ? g_bsum[i] : 0;
    int x = v;
    #pragma unroll
    for (int o = 1; o < 32; o <<= 1) {
        int y = __shfl_up_sync(0xffffffffu, x, o);
        if ((i & 31) >= o) x += y;
    }
    __shared__ int ws[4];
    if ((i & 31) == 31) ws[i >> 5] = x;
    __syncthreads();
    int off = 0;
    for (int w = 0; w < (i >> 5); w++) off += ws[w];
    if (i < nb) g_bsum[i] = x - v + off;  // exclusive
}

__global__ void k_scanC(int E) {
    int i = blockIdx.x * 1024 + threadIdx.x;
    if (i < NN) {
        g_rowptr[i] += g_bsum[blockIdx.x];
        g_deg[i] = 0;  // reset as scatter cursor
    }
    if (i == 0) g_rowptr[NN] = E;
}

__global__ void k_scatter(const int* __restrict__ src, const int* __restrict__ dst,
                          const float* __restrict__ adj, int E) {
    for (int e = blockIdx.x * blockDim.x + threadIdx.x; e < E;
         e += gridDim.x * blockDim.x) {
        int r = src[e];
        int pos = g_rowptr[r] + atomicAdd(&g_deg[r], 1);
        g_col[pos]  = dst[e];
        float a = adj[e];
        g_aval[pos] = a;
        g_mem[pos]  = a;   // memory starts as adjacency values
    }
}

// ---------------- init embeddings ----------------

__global__ void k_init_emb(const float* __restrict__ ue, const float* __restrict__ ie) {
    for (int i = blockIdx.x * blockDim.x + threadIdx.x; i < NN * D;
         i += gridDim.x * blockDim.x) {
        float v = (i < N_USER * D) ? ue[i] : ie[i - N_USER * D];
        g_embA[i]  = v;
        g_light[i] = v;   // embs[0] contribution to the mean-sum
    }
}

// ---------------- per-layer kernels ----------------

// reciprocal norms (warp per node)
__global__ void k_rnorm(int cur) {
    const float* emb = cur ? g_embB : g_embA;
    int row = blockIdx.x * (blockDim.x >> 5) + (threadIdx.x >> 5);
    if (row >= NN) return;
    int lane = threadIdx.x & 31;
    float2 v = *(const float2*)(emb + row * D + lane * 2);
    float s = v.x * v.x + v.y * v.y;
    #pragma unroll
    for (int o = 16; o; o >>= 1) s += __shfl_xor_sync(0xffffffffu, s, o);
    if (lane == 0) g_rnorm[row] = (s > 1e-24f) ? rsqrtf(s) : 0.f;
}

// pass 1: per-edge cosine + row L1 sums.
// Warp per row; 4 edge-groups of 8 lanes; each lane holds 8 dims (2x float4).
__global__ void k_cos(int cur) {
    const float* __restrict__ emb = cur ? g_embB : g_embA;
    int row = blockIdx.x * (blockDim.x >> 5) + (threadIdx.x >> 5);
    if (row >= NN) return;
    int lane = threadIdx.x & 31;
    int g = lane >> 3, sl = lane & 7;
    unsigned gmask = 0xFFu << (g * 8);

    const float* rp = emb + row * D + sl * 8;
    float4 es0 = *(const float4*)(rp);
    float4 es1 = *(const float4*)(rp + 4);
    float rn_r = g_rnorm[row];

    int beg = g_rowptr[row], end = g_rowptr[row + 1];
    int nit = (end - beg + 3) >> 2;
    float rs = 0.f;
    for (int it = 0; it < nit; it++) {
        int pos = beg + it * 4 + g;
        bool act = pos < end;
        int c = act ? g_col[pos] : row;
        const float* cp = emb + c * D + sl * 8;
        float4 d0 = *(const float4*)(cp);
        float4 d1 = *(const float4*)(cp + 4);
        float p = es0.x * d0.x + es0.y * d0.y + es0.z * d0.z + es0.w * d0.w
                + es1.x * d1.x + es1.y * d1.y + es1.z * d1.z + es1.w * d1.w;
        p += __shfl_xor_sync(gmask, p, 1);
        p += __shfl_xor_sync(gmask, p, 2);
        p += __shfl_xor_sync(gmask, p, 4);
        float cs = p * rn_r * g_rnorm[c];
        if (!act) cs = 0.f;
        if (act && sl == 0) g_cos[pos] = cs;
        rs += fabsf(cs);
    }
    // all 8 lanes of a group hold the same rs; combine the 4 groups
    rs += __shfl_xor_sync(0xffffffffu, rs, 8);
    rs += __shfl_xor_sync(0xffffffffu, rs, 16);
    if (lane == 0) g_rowsum[row] = rs;
}

// invert rowsums in place (reference: divide by rowsum iff > 0, else by 1)
__global__ void k_rsinv() {
    int i = blockIdx.x * blockDim.x + threadIdx.x;
    if (i < NN) {
        float rs = g_rowsum[i];
        g_rowsum[i] = (rs > 0.f) ? 1.f / rs : 1.f;
    }
}

// pass 2: coef -> prune -> mem EMA -> SpMM row accumulate (+ light sum)
__global__ void k_spmm(int cur, const float* __restrict__ W, const float* __restrict__ B) {
    const float* __restrict__ embin = cur ? g_embB : g_embA;
    float* embout                   = cur ? g_embA : g_embB;
    int row = blockIdx.x * (blockDim.x >> 5) + (threadIdx.x >> 5);
    if (row >= NN) return;
    int lane = threadIdx.x & 31;
    int g = lane >> 3, sl = lane & 7;

    float w0 = W[0], w1 = W[1], bb = B[0];
    float invr = g_rowsum[row];   // already reciprocal
    int beg = g_rowptr[row], end = g_rowptr[row + 1];
    int nit = (end - beg + 3) >> 2;

    float a0 = 0.f, a1 = 0.f, a2 = 0.f, a3 = 0.f;
    float a4 = 0.f, a5 = 0.f, a6 = 0.f, a7 = 0.f;
    for (int it = 0; it < nit; it++) {
        int pos = beg + it * 4 + g;
        bool act = pos < end;
        int posc = act ? pos : beg;
        int c = g_col[posc];
        float cs = g_cos[posc];
        float c1 = cs * invr;
        float c2 = cs * g_rowsum[c];               // cos symmetric: coef[rev] = cs / rowsum[dst]
        float z = w0 * c1 + w1 * c2 + bb;          // sigmoid(z)>0.5 <=> z>0
        float coef = (z > 0.f) ? c1 : 0.f;
        float m = 0.5f * (g_mem[posc] + coef);
        if (act && sl == 0) g_mem[pos] = m;
        float gv = act ? m * g_aval[posc] : 0.f;
        const float* cp = embin + c * D + sl * 8;
        float4 d0 = *(const float4*)(cp);
        float4 d1 = *(const float4*)(cp + 4);
        a0 += gv * d0.x; a1 += gv * d0.y; a2 += gv * d0.z; a3 += gv * d0.w;
        a4 += gv * d1.x; a5 += gv * d1.y; a6 += gv * d1.z; a7 += gv * d1.w;
    }
    // combine the 4 groups (same dims live in lanes sl, sl+8, sl+16, sl+24)
    #pragma unroll
    for (int o = 8; o <= 16; o <<= 1) {
        a0 += __shfl_xor_sync(0xffffffffu, a0, o);
        a1 += __shfl_xor_sync(0xffffffffu, a1, o);
        a2 += __shfl_xor_sync(0xffffffffu, a2, o);
        a3 += __shfl_xor_sync(0xffffffffu, a3, o);
        a4 += __shfl_xor_sync(0xffffffffu, a4, o);
        a5 += __shfl_xor_sync(0xffffffffu, a5, o);
        a6 += __shfl_xor_sync(0xffffffffu, a6, o);
        a7 += __shfl_xor_sync(0xffffffffu, a7, o);
    }
    if (g == 0) {
        float* op = embout + row * D + sl * 8;
        *(float4*)(op)     = make_float4(a0, a1, a2, a3);
        *(float4*)(op + 4) = make_float4(a4, a5, a6, a7);
        float* lp = g_light + row * D + sl * 8;
        float4 l0 = *(float4*)(lp);
        float4 l1 = *(float4*)(lp + 4);
        l0.x += a0; l0.y += a1; l0.z += a2; l0.w += a3;
        l1.x += a4; l1.y += a5; l1.z += a6; l1.w += a7;
        *(float4*)(lp)     = l0;
        *(float4*)(lp + 4) = l1;
    }
}

// ---------------- final: gather + sigmoid GEMM ----------------

__global__ void k_gather(const int* __restrict__ users, const int* __restrict__ items,
                         int Bu, int Bi) {
    int i = blockIdx.x * blockDim.x + threadIdx.x;
    int totU = Bu * D;
    if (i < totU) {
        int u = users[i >> 6];
        g_U[i] = 0.25f * g_light[u * D + (i & 63)];
    } else {
        int j = i - totU;
        if (j < Bi * D) {
            int it = items[j >> 6];
            g_I[j] = 0.25f * g_light[(N_USER + it) * D + (j & 63)];
        }
    }
}

__global__ void k_gemm(float* __restrict__ out, int Bu, int Bi) {
    __shared__ float As[64][65];
    __shared__ float Bs[64][65];
    int tx = threadIdx.x, ty = threadIdx.y;       // 16x16
    int t = ty * 16 + tx;
    int rowBase = blockIdx.y * 64, colBase = blockIdx.x * 64;
    #pragma unroll
    for (int i = 0; i < 4; i++) {
        int j = t + i * 256;       // float4 slot 0..1023
        int r = j >> 4;
        int kq = (j & 15) * 4;
        float4 a = (rowBase + r < Bu) ? *(const float4*)(g_U + (rowBase + r) * 64 + kq)
                                      : make_float4(0, 0, 0, 0);
        As[r][kq] = a.x; As[r][kq + 1] = a.y; As[r][kq + 2] = a.z; As[r][kq + 3] = a.w;
        float4 b = (colBase + r < Bi) ? *(const float4*)(g_I + (colBase + r) * 64 + kq)
                                      : make_float4(0, 0, 0, 0);
        Bs[r][kq] = b.x; Bs[r][kq + 1] = b.y; Bs[r][kq + 2] = b.z; Bs[r][kq + 3] = b.w;
    }
    __syncthreads();
    float acc[4][4] = {};
    #pragma unroll
    for (int k = 0; k < 64; k++) {
        float a0 = As[ty * 4 + 0][k], a1 = As[ty * 4 + 1][k];
        float a2 = As[ty * 4 + 2][k], a3 = As[ty * 4 + 3][k];
        float b0 = Bs[tx * 4 + 0][k], b1 = Bs[tx * 4 + 1][k];
        float b2 = Bs[tx * 4 + 2][k], b3 = Bs[tx * 4 + 3][k];
        acc[0][0] += a0 * b0; acc[0][1] += a0 * b1; acc[0][2] += a0 * b2; acc[0][3] += a0 * b3;
        acc[1][0] += a1 * b0; acc[1][1] += a1 * b1; acc[1][2] += a1 * b2; acc[1][3] += a1 * b3;
        acc[2][0] += a2 * b0; acc[2][1] += a2 * b1; acc[2][2] += a2 * b2; acc[2][3] += a2 * b3;
        acc[3][0] += a3 * b0; acc[3][1] += a3 * b1; acc[3][2] += a3 * b2; acc[3][3] += a3 * b3;
    }
    #pragma unroll
    for (int i = 0; i < 4; i++)
        #pragma unroll
        for (int j = 0; j < 4; j++) {
            int r = rowBase + ty * 4 + i;
            int c = colBase + tx * 4 + j;
            if (r < Bu && c < Bi)
                out[r * Bi + c] = 1.f / (1.f + expf(-acc[i][j]));
        }
}

// ---------------- launch ----------------

extern "C" void kernel_launch(void* const* d_in, const int* in_sizes, int n_in,
                              void* d_out, int out_size) {
    const int*   users    = (const int*)d_in[0];
    const int*   items    = (const int*)d_in[1];
    const float* user_emb = (const float*)d_in[2];
    const float* item_emb = (const float*)d_in[3];
    const float* W_prune  = (const float*)d_in[4];
    const float* b_prune  = (const float*)d_in[5];
    const int*   src      = (const int*)d_in[6];
    const int*   dst      = (const int*)d_in[7];
    // d_in[8] = rev_perm (unused: cosine is symmetric)
    const float* adj_vals = (const float*)d_in[9];

    int Bu = in_sizes[0];
    int Bi = in_sizes[1];
    int E  = in_sizes[6];

    float* out = (float*)d_out;

    int ebl = (E + 1023) / 1024;

    // CSR build
    k_zero_deg<<<NB_SCAN, 1024>>>();
    k_hist<<<ebl, 1024>>>(src, E);
    k_scanA<<<NB_SCAN, 1024>>>();
    k_scanB<<<1, 128>>>(NB_SCAN);
    k_scanC<<<NB_SCAN, 1024>>>(E);
    k_scatter<<<ebl, 1024>>>(src, dst, adj_vals, E);

    // init embeddings + light accumulator
    k_init_emb<<<(NN * D + 1023) / 1024, 1024>>>(user_emb, item_emb);

    // 3 propagation layers (warp per node row, 4-edge groups)
    int rowsblocks = (NN + 7) / 8;   // 8 warps per 256-thread block
    for (int l = 0; l < 3; l++) {
        int cur = l & 1;
        k_rnorm<<<rowsblocks, 256>>>(cur);
        k_cos<<<rowsblocks, 256>>>(cur);
        k_rsinv<<<NB_SCAN, 1024>>>();
        k_spmm<<<rowsblocks, 256>>>(cur, W_prune, b_prune);
    }

    // gather query embeddings (with /4 mean fold), then sigmoid GEMM
    int tot = (Bu + Bi) * D;
    k_gather<<<(tot + 255) / 256, 256>>>(users, items, Bu, Bi);
    dim3 gblk(16, 16);
    dim3 ggrd((Bi + 63) / 64, (Bu + 63) / 64);
    k_gemm<<<ggrd, gblk>>>(out, Bu, Bi);
}